// round 14
// baseline (speedup 1.0000x reference)
#include <cuda_runtime.h>
#include <cuda_bf16.h>
#include <cstdint>
#include <math.h>

#define T_STEPS 512
#define BATCH   64
#define IN_F    512
#define HID     512
#define GATES   1024

// scan decomposition: 4 independent batch groups x 16 CTAs
#define N_GROUPS   4
#define GROUP_CTAS 16
#define GB         16
#define CTA_COLS   32
#define SCAN_BLOCKS 64

// gi tensor-core GEMM tiling
#define GI_KC    32
#define GSTRIDE  36
#define PLANE_U  (128 * GSTRIDE)          // uints per staged plane (4608)
#define GI_BLOCKS 2048                    // 8 n-tiles x 256 m-tiles

// scan smem layout
#define HROW        520
#define PLANE_USH   (GB * HROW)
#define RED_OFF_B   (2 * PLANE_USH * 2)
// fused smem: max(scan 135168, gi 2-stage 2*4*4608*4 = 147456)
#define FUSED_SMEM_BYTES (2 * 4 * PLANE_U * 4 + 1024)

// scratch
__device__ float g_gi[(size_t)T_STEPS * BATCH * GATES];
__device__ unsigned short g_hhi[(size_t)T_STEPS * BATCH * HID];
__device__ unsigned short g_hlo[(size_t)T_STEPS * BATCH * HID];
__device__ unsigned g_xhi[(size_t)T_STEPS * BATCH * IN_F];   // X tf32 hi plane
__device__ unsigned g_xlo[(size_t)T_STEPS * BATCH * IN_F];   // X tf32 lo plane
__device__ unsigned g_whi[(size_t)GATES * IN_F];             // Wih tf32 hi plane
__device__ unsigned g_wlo[(size_t)GATES * IN_F];             // Wih tf32 lo plane
__device__ unsigned int g_bars[N_GROUPS * 32];
__device__ unsigned int g_gi_cnt[256 * 8];
__device__ unsigned int g_scan_done;

__device__ __forceinline__ unsigned ld_acquire_gpu(const unsigned* p) {
    unsigned v;
    asm volatile("ld.acquire.gpu.global.u32 %0, [%1];" : "=r"(v) : "l"(p));
    return v;
}
__device__ __forceinline__ void red_release_gpu_add1(unsigned* p) {
    asm volatile("red.release.gpu.global.add.u32 [%0], 1;" :: "l"(p) : "memory");
}
__device__ __forceinline__ unsigned f2tf32(float x) {
    unsigned r;
    asm("cvt.rna.tf32.f32 %0, %1;" : "=r"(r) : "f"(x));
    return r;
}
__device__ __forceinline__ void cvt_split(float x, unsigned& hi, unsigned& lo) {
    hi = f2tf32(x);
    lo = f2tf32(x - __uint_as_float(hi));
}
__device__ __forceinline__ uint32_t smem_u32(const void* p) {
    uint32_t a;
    asm("{.reg .u64 t; cvta.to.shared.u64 t, %1; cvt.u32.u64 %0, t;}" : "=r"(a) : "l"(p));
    return a;
}
__device__ __forceinline__ void ldsm4(unsigned* r, uint32_t addr) {
    asm volatile("ldmatrix.sync.aligned.m8n8.x4.shared.b16 {%0,%1,%2,%3}, [%4];"
                 : "=r"(r[0]), "=r"(r[1]), "=r"(r[2]), "=r"(r[3]) : "r"(addr));
}
__device__ __forceinline__ void mma_tf32(float* c, const unsigned* a, const unsigned* b) {
    asm volatile("mma.sync.aligned.m16n8k8.row.col.f32.tf32.tf32.f32 "
                 "{%0,%1,%2,%3}, {%4,%5,%6,%7}, {%8,%9}, {%0,%1,%2,%3};"
                 : "+f"(c[0]), "+f"(c[1]), "+f"(c[2]), "+f"(c[3])
                 : "r"(a[0]), "r"(a[1]), "r"(a[2]), "r"(a[3]), "r"(b[0]), "r"(b[1]));
}
__device__ __forceinline__ void mma_bf16(float* c, const unsigned* a, const unsigned* b) {
    asm volatile("mma.sync.aligned.m16n8k16.row.col.f32.bf16.bf16.f32 "
                 "{%0,%1,%2,%3}, {%4,%5,%6,%7}, {%8,%9}, {%0,%1,%2,%3};"
                 : "+f"(c[0]), "+f"(c[1]), "+f"(c[2]), "+f"(c[3])
                 : "r"(a[0]), "r"(a[1]), "r"(a[2]), "r"(a[3]), "r"(b[0]), "r"(b[1]));
}
__device__ __forceinline__ void cp_async16(uint32_t smem, const void* gptr) {
    asm volatile("cp.async.cg.shared.global [%0], [%1], 16;" :: "r"(smem), "l"(gptr) : "memory");
}
__device__ __forceinline__ void cp_commit() {
    asm volatile("cp.async.commit_group;" ::: "memory");
}
__device__ __forceinline__ void cp_commit_wait() {
    asm volatile("cp.async.commit_group;\ncp.async.wait_group 0;" ::: "memory");
}

// ============ pre-pass: split X / Wih into tf32 hi/lo planes ============
__global__ __launch_bounds__(256) void conv_x(const float* __restrict__ X) {
    const size_t i4 = (size_t)blockIdx.x * 256 + threadIdx.x;   // float4 index
    const float4 v = *(const float4*)&X[i4 * 4];
    uint4 h, l;
    cvt_split(v.x, h.x, l.x); cvt_split(v.y, h.y, l.y);
    cvt_split(v.z, h.z, l.z); cvt_split(v.w, h.w, l.w);
    *(uint4*)&g_xhi[i4 * 4] = h;
    *(uint4*)&g_xlo[i4 * 4] = l;
}
__global__ __launch_bounds__(256) void conv_w(const float* __restrict__ W) {
    const size_t i4 = (size_t)blockIdx.x * 256 + threadIdx.x;
    const float4 v = *(const float4*)&W[i4 * 4];
    uint4 h, l;
    cvt_split(v.x, h.x, l.x); cvt_split(v.y, h.y, l.y);
    cvt_split(v.z, h.z, l.z); cvt_split(v.w, h.w, l.w);
    *(uint4*)&g_whi[i4 * 4] = h;
    *(uint4*)&g_wlo[i4 * 4] = l;
}

// ===================== gi GEMM role: cp.async pipelined planes ============
__device__ void gi_role(unsigned char* smraw, int g, const float* __restrict__ bih) {
    unsigned* gsm = (unsigned*)smraw;     // 2 stages x [Ahi|Alo|Bhi|Blo] x 4608

    const int bx = g & 7;                 // n-tile
    const int by = g >> 3;                // m-tile = time pair
    const int tid  = threadIdx.x;
    const int lane = tid & 31;
    const int wid  = tid >> 5;
    const int warpM = (wid & 3) * 32;
    const int warpN = (wid >> 2) * 32;
    const int Mb = by * 128;
    const int Nb = bx * 128;

    const int aRow = warpM + (lane & 15);
    const int aColOff = (lane >> 4) << 2;
    const int bRow = warpN + ((lane >> 4) << 3) + (lane & 7);
    const int bColOff = ((lane >> 3) & 1) << 2;

    float acc[2][4][4];
    #pragma unroll
    for (int mt = 0; mt < 2; mt++)
        #pragma unroll
        for (int nt = 0; nt < 4; nt++)
            #pragma unroll
            for (int i = 0; i < 4; i++) acc[mt][nt][i] = 0.f;

    // staging map: plane = 128 rows x 8 16B-chunks = 1024 chunks; 2 per thread
    const int srow0 = tid >> 3, sc40 = (tid & 7) * 4;
    const int srow1 = (tid + 512) >> 3, sc41 = ((tid + 512) & 7) * 4;

    // issue stage for chunk c into buffer st
    auto issue_stage = [&](int c, int st) {
        const int k0 = c * GI_KC;
        unsigned* base = gsm + st * (4 * PLANE_U);
        {
            const int soff = srow0 * GSTRIDE + sc40;
            cp_async16(smem_u32(base + soff),               &g_xhi[(size_t)(Mb + srow0) * IN_F + k0 + sc40]);
            cp_async16(smem_u32(base + PLANE_U + soff),     &g_xlo[(size_t)(Mb + srow0) * IN_F + k0 + sc40]);
            cp_async16(smem_u32(base + 2 * PLANE_U + soff), &g_whi[(size_t)(Nb + srow0) * IN_F + k0 + sc40]);
            cp_async16(smem_u32(base + 3 * PLANE_U + soff), &g_wlo[(size_t)(Nb + srow0) * IN_F + k0 + sc40]);
        }
        {
            const int soff = srow1 * GSTRIDE + sc41;
            cp_async16(smem_u32(base + soff),               &g_xhi[(size_t)(Mb + srow1) * IN_F + k0 + sc41]);
            cp_async16(smem_u32(base + PLANE_U + soff),     &g_xlo[(size_t)(Mb + srow1) * IN_F + k0 + sc41]);
            cp_async16(smem_u32(base + 2 * PLANE_U + soff), &g_whi[(size_t)(Nb + srow1) * IN_F + k0 + sc41]);
            cp_async16(smem_u32(base + 3 * PLANE_U + soff), &g_wlo[(size_t)(Nb + srow1) * IN_F + k0 + sc41]);
        }
        cp_commit();
    };

    issue_stage(0, 0);
    for (int c = 0; c < IN_F / GI_KC; c++) {
        if (c + 1 < IN_F / GI_KC) {
            issue_stage(c + 1, (c + 1) & 1);
            asm volatile("cp.async.wait_group 1;" ::: "memory");
        } else {
            asm volatile("cp.async.wait_group 0;" ::: "memory");
        }
        __syncthreads();

        unsigned* Ahi = gsm + (c & 1) * (4 * PLANE_U);
        unsigned* Alo = Ahi + PLANE_U;
        unsigned* Bhi = Ahi + 2 * PLANE_U;
        unsigned* Blo = Ahi + 3 * PLANE_U;

        #pragma unroll
        for (int k8 = 0; k8 < GI_KC / 8; k8++) {
            const int kb = k8 * 8;
            unsigned ah[2][4], al[2][4], bh[4][2], bl[4][2];
            #pragma unroll
            for (int mt = 0; mt < 2; mt++) {
                const int off = (aRow + mt * 16) * GSTRIDE + kb + aColOff;
                ldsm4(ah[mt], smem_u32(&Ahi[off]));
                ldsm4(al[mt], smem_u32(&Alo[off]));
            }
            #pragma unroll
            for (int np = 0; np < 2; np++) {
                const int off = (bRow + np * 16) * GSTRIDE + kb + bColOff;
                unsigned r[4];
                ldsm4(r, smem_u32(&Bhi[off]));
                bh[2 * np][0] = r[0]; bh[2 * np][1] = r[1];
                bh[2 * np + 1][0] = r[2]; bh[2 * np + 1][1] = r[3];
                ldsm4(r, smem_u32(&Blo[off]));
                bl[2 * np][0] = r[0]; bl[2 * np][1] = r[1];
                bl[2 * np + 1][0] = r[2]; bl[2 * np + 1][1] = r[3];
            }
            #pragma unroll
            for (int mt = 0; mt < 2; mt++)
                #pragma unroll
                for (int nt = 0; nt < 4; nt++) {
                    mma_tf32(acc[mt][nt], ah[mt], bh[nt]);
                    mma_tf32(acc[mt][nt], ah[mt], bl[nt]);
                    mma_tf32(acc[mt][nt], al[mt], bh[nt]);
                }
        }
        __syncthreads();   // buffer (c&1) free for stage c+2
    }

    #pragma unroll
    for (int mt = 0; mt < 2; mt++)
        #pragma unroll
        for (int nt = 0; nt < 4; nt++) {
            const int gr = Mb + warpM + mt * 16 + (lane >> 2);
            const int gc = Nb + warpN + nt * 8 + 2 * (lane & 3);
            const float2 bv = *(const float2*)&bih[gc];
            float2 v0, v1;
            v0.x = acc[mt][nt][0] + bv.x; v0.y = acc[mt][nt][1] + bv.y;
            v1.x = acc[mt][nt][2] + bv.x; v1.y = acc[mt][nt][3] + bv.y;
            *(float2*)&g_gi[(size_t)gr * GATES + gc] = v0;
            *(float2*)&g_gi[(size_t)(gr + 8) * GATES + gc] = v1;
        }

    __threadfence();
    __syncthreads();
    if (tid == 0) red_release_gpu_add1(&g_gi_cnt[by * 8]);
}

// ===================== scan role (body verified R12/R13, frozen) ==========
__device__ void scan_role(unsigned char* smraw,
                          const float* __restrict__ Whh,
                          const float* __restrict__ bhh,
                          float* __restrict__ out) {
    unsigned short* hhi = (unsigned short*)smraw;
    unsigned short* hlo = hhi + PLANE_USH;
    float* red = (float*)(smraw + RED_OFF_B);

    const int tid  = threadIdx.x;
    const int lane = tid & 31;
    const int wid  = tid >> 5;
    const int ksl  = wid >> 2;
    const int ng   = wid & 3;
    const int grp  = blockIdx.x >> 4;
    const int cg   = blockIdx.x & 15;
    const int bg0  = grp * GB;
    const int j0   = cg * CTA_COLS;
    unsigned* bar  = &g_bars[grp * 32];

    unsigned short* Whi_s = hhi;
    unsigned short* Wlo_s = hhi + 64 * HROW;
    for (int i = tid; i < 64 * 512; i += 512) {
        const int n = i >> 9, c = i & 511;
        const int gr = (n < CTA_COLS) ? (j0 + n) : (HID + j0 + (n - CTA_COLS));
        const float w = Whh[(size_t)gr * HID + c];
        const __nv_bfloat16 h16 = __float2bfloat16(w);
        const __nv_bfloat16 l16 = __float2bfloat16(w - __bfloat162float(h16));
        Whi_s[n * HROW + c] = __bfloat16_as_ushort(h16);
        Wlo_s[n * HROW + c] = __bfloat16_as_ushort(l16);
    }
    __syncthreads();
    unsigned wbh[8][4], wbl[8][4];
    {
        const int brow = ng * 16 + (lane & 7) + ((lane >> 4) << 3);
        const int bcol = ((lane >> 3) & 1) * 8;
        #pragma unroll
        for (int s = 0; s < 8; s++) {
            const int k0 = ksl * 128 + s * 16;
            ldsm4(wbh[s], smem_u32(&Whi_s[brow * HROW + k0 + bcol]));
            ldsm4(wbl[s], smem_u32(&Wlo_s[brow * HROW + k0 + bcol]));
        }
    }
    __syncthreads();

    const int arow  = (lane & 7) + 8 * ((lane >> 3) & 1);
    const int acol8 = (lane >> 4) * 8;
    const uint32_t ahi_base = smem_u32(&hhi[arow * HROW]);
    const uint32_t alo_base = smem_u32(&hlo[arow * HROW]);

    const int jl = tid & 31;
    const int bl = tid >> 5;
    const int b  = bg0 + bl;
    const int jg = j0 + jl;
    const float bhf = bhh[jg];
    const float bhn = bhh[HID + jg];

    if (tid == 0) {
        while (ld_acquire_gpu(&g_gi_cnt[0]) < 8) __nanosleep(64);
    }
    __syncthreads();
    int last_ready = 0;

    float gif = g_gi[((size_t)b << 10) + jg];
    float gin = g_gi[((size_t)b << 10) + HID + jg];

    for (int t = 0; t < T_STEPS; t++) {
        if (t > 0) {
            __syncthreads();
            if (tid == 0) {
                red_release_gpu_add1(bar);
                const unsigned target = (unsigned)GROUP_CTAS * (unsigned)t;
                while (ld_acquire_gpu(bar) < target) __nanosleep(32);
                const int qn = ((t + 1 < T_STEPS) ? (t + 1) : t) >> 1;
                if (qn > last_ready) {
                    while (ld_acquire_gpu(&g_gi_cnt[qn * 8]) < 8) __nanosleep(32);
                    last_ready = qn;
                }
            }
            __syncthreads();
        }

        const int tn = (t + 1 < T_STEPS) ? (t + 1) : t;
        const float gif_n = g_gi[((size_t)tn << 16) + ((size_t)b << 10) + jg];
        const float gin_n = g_gi[((size_t)tn << 16) + ((size_t)b << 10) + HID + jg];

        float accf = 0.f, accn = 0.f;
        if (t > 0) {
            const unsigned short* ph = g_hhi + ((size_t)(t - 1) * BATCH + bg0) * HID;
            const unsigned short* pl = g_hlo + ((size_t)(t - 1) * BATCH + bg0) * HID;
            #pragma unroll
            for (int i = 0; i < 2; i++) {
                const int idx = tid + 512 * i;
                const int br = idx >> 6, c = idx & 63;
                cp_async16(smem_u32(&hhi[br * HROW + c * 8]), ph + idx * 8);
                cp_async16(smem_u32(&hlo[br * HROW + c * 8]), pl + idx * 8);
            }
            cp_commit_wait();
            __syncthreads();

            float c4[2][4] = {{0.f, 0.f, 0.f, 0.f}, {0.f, 0.f, 0.f, 0.f}};
            #pragma unroll
            for (int s = 0; s < 8; s++) {
                const int k0 = ksl * 128 + s * 16;
                unsigned ah[4], al[4];
                ldsm4(ah, ahi_base + (k0 + acol8) * 2);
                ldsm4(al, alo_base + (k0 + acol8) * 2);
                #pragma unroll
                for (int nt = 0; nt < 2; nt++) {
                    mma_bf16(c4[nt], ah, &wbh[s][2 * nt]);
                    mma_bf16(c4[nt], ah, &wbl[s][2 * nt]);
                    mma_bf16(c4[nt], al, &wbh[s][2 * nt]);
                }
            }
            const int rm = lane >> 2;
            const int rn = ng * 16 + 2 * (lane & 3);
            #pragma unroll
            for (int nt = 0; nt < 2; nt++) {
                *(float2*)&red[ksl * (GB * 64) + rm * 64 + rn + nt * 8] =
                    make_float2(c4[nt][0], c4[nt][1]);
                *(float2*)&red[ksl * (GB * 64) + (rm + 8) * 64 + rn + nt * 8] =
                    make_float2(c4[nt][2], c4[nt][3]);
            }
            __syncthreads();

            #pragma unroll
            for (int k = 0; k < 4; k++) {
                accf += red[k * (GB * 64) + bl * 64 + jl];
                accn += red[k * (GB * 64) + bl * 64 + CTA_COLS + jl];
            }
        }

        {
            const float f  = 1.f / (1.f + expf(-(gif + accf + bhf)));
            const float hv = tanhf(gin + f * (accn + bhn));
            out[((size_t)t * BATCH + b) * HID + jg] = hv;
            const __nv_bfloat16 h16 = __float2bfloat16(hv);
            const __nv_bfloat16 l16 = __float2bfloat16(hv - __bfloat162float(h16));
            g_hhi[(size_t)t * BATCH * HID + b * HID + jg] = __bfloat16_as_ushort(h16);
            g_hlo[(size_t)t * BATCH * HID + b * HID + jg] = __bfloat16_as_ushort(l16);
        }
        gif = gif_n;
        gin = gin_n;
    }

    __syncthreads();
    if (tid == 0) {
        const unsigned r = atomicAdd(bar, 1u);
        if (r == (unsigned)GROUP_CTAS * (unsigned)T_STEPS - 1u)
            *((volatile unsigned*)bar) = 0u;
        red_release_gpu_add1(&g_scan_done);
        if (blockIdx.x == 0) {
            while (ld_acquire_gpu(&g_scan_done) < (unsigned)SCAN_BLOCKS) __nanosleep(64);
            for (int q = 0; q < 256; q++)
                *((volatile unsigned*)&g_gi_cnt[q * 8]) = 0u;
            *((volatile unsigned*)&g_scan_done) = 0u;
        }
    }
}

// ===================== fused kernel =====================
__global__ __launch_bounds__(512) void fused_mgu(const float* __restrict__ bih,
                                                 const float* __restrict__ Whh,
                                                 const float* __restrict__ bhh,
                                                 float* __restrict__ out) {
    extern __shared__ unsigned char smraw[];
    if (blockIdx.x < SCAN_BLOCKS) {
        scan_role(smraw, Whh, bhh, out);
    } else {
        gi_role(smraw, (int)blockIdx.x - SCAN_BLOCKS, bih);
    }
}

extern "C" void kernel_launch(void* const* d_in, const int* in_sizes, int n_in,
                              void* d_out, int out_size) {
    const float* X   = (const float*)d_in[0];  // (512, 64, 512)
    const float* Wih = (const float*)d_in[1];  // (1024, 512)
    const float* Whh = (const float*)d_in[2];  // (1024, 512)
    const float* bih = (const float*)d_in[3];  // (1024,)
    const float* bhh = (const float*)d_in[4];  // (1024,)
    float* out = (float*)d_out;                // (512, 64, 512)

    cudaFuncSetAttribute(fused_mgu,
                         cudaFuncAttributeMaxDynamicSharedMemorySize, FUSED_SMEM_BYTES);

    // pre-pass: split X / Wih into tf32 hi/lo planes (memory-bound, ~35us)
    conv_x<<<(T_STEPS * BATCH * IN_F / 4) / 256, 256>>>(X);
    conv_w<<<(GATES * IN_F / 4) / 256, 256>>>(Wih);

    fused_mgu<<<SCAN_BLOCKS + GI_BLOCKS, 512, FUSED_SMEM_BYTES>>>(
        bih, Whh, bhh, out);
}

// round 15
// speedup vs baseline: 1.1055x; 1.1055x over previous
#include <cuda_runtime.h>
#include <cuda_bf16.h>
#include <cstdint>
#include <math.h>

#define T_STEPS 512
#define BATCH   64
#define IN_F    512
#define HID     512
#define GATES   1024

// scan decomposition: 4 independent batch groups x 16 CTAs
#define N_GROUPS   4
#define GROUP_CTAS 16
#define GB         16
#define CTA_COLS   32
#define SCAN_BLOCKS 64

// gi tensor-core GEMM tiling
#define GI_KC    32
#define GSTRIDE  36
#define PLANE_U  (128 * GSTRIDE)          // uints per staged plane (4608)
#define GI_BLOCKS 2048                    // 8 n-tiles x 256 m-tiles
#define N_CHUNKS (IN_F / GI_KC)           // 16

// scan smem layout
#define HROW        520
#define PLANE_USH   (GB * HROW)
#define RED_OFF_B   (2 * PLANE_USH * 2)
// fused smem: max(scan 135168, gi 2-stage 2*4*4608*4 = 147456)
#define FUSED_SMEM_BYTES (2 * 4 * PLANE_U * 4 + 1024)

// scratch
__device__ float g_gi[(size_t)T_STEPS * BATCH * GATES];
__device__ unsigned short g_hhi[(size_t)T_STEPS * BATCH * HID];
__device__ unsigned short g_hlo[(size_t)T_STEPS * BATCH * HID];
__device__ unsigned int g_bars[N_GROUPS * 32];
__device__ unsigned int g_gi_cnt[256 * 8];
__device__ unsigned int g_scan_done;

__device__ __forceinline__ unsigned ld_acquire_gpu(const unsigned* p) {
    unsigned v;
    asm volatile("ld.acquire.gpu.global.u32 %0, [%1];" : "=r"(v) : "l"(p));
    return v;
}
__device__ __forceinline__ void red_release_gpu_add1(unsigned* p) {
    asm volatile("red.release.gpu.global.add.u32 [%0], 1;" :: "l"(p) : "memory");
}
__device__ __forceinline__ unsigned f2tf32(float x) {
    unsigned r;
    asm("cvt.rna.tf32.f32 %0, %1;" : "=r"(r) : "f"(x));
    return r;
}
__device__ __forceinline__ void cvt_split(float x, unsigned& hi, unsigned& lo) {
    hi = f2tf32(x);
    lo = f2tf32(x - __uint_as_float(hi));
}
__device__ __forceinline__ uint32_t smem_u32(const void* p) {
    uint32_t a;
    asm("{.reg .u64 t; cvta.to.shared.u64 t, %1; cvt.u32.u64 %0, t;}" : "=r"(a) : "l"(p));
    return a;
}
__device__ __forceinline__ void ldsm4(unsigned* r, uint32_t addr) {
    asm volatile("ldmatrix.sync.aligned.m8n8.x4.shared.b16 {%0,%1,%2,%3}, [%4];"
                 : "=r"(r[0]), "=r"(r[1]), "=r"(r[2]), "=r"(r[3]) : "r"(addr));
}
__device__ __forceinline__ void mma_tf32(float* c, const unsigned* a, const unsigned* b) {
    asm volatile("mma.sync.aligned.m16n8k8.row.col.f32.tf32.tf32.f32 "
                 "{%0,%1,%2,%3}, {%4,%5,%6,%7}, {%8,%9}, {%0,%1,%2,%3};"
                 : "+f"(c[0]), "+f"(c[1]), "+f"(c[2]), "+f"(c[3])
                 : "r"(a[0]), "r"(a[1]), "r"(a[2]), "r"(a[3]), "r"(b[0]), "r"(b[1]));
}
__device__ __forceinline__ void mma_bf16(float* c, const unsigned* a, const unsigned* b) {
    asm volatile("mma.sync.aligned.m16n8k16.row.col.f32.bf16.bf16.f32 "
                 "{%0,%1,%2,%3}, {%4,%5,%6,%7}, {%8,%9}, {%0,%1,%2,%3};"
                 : "+f"(c[0]), "+f"(c[1]), "+f"(c[2]), "+f"(c[3])
                 : "r"(a[0]), "r"(a[1]), "r"(a[2]), "r"(a[3]), "r"(b[0]), "r"(b[1]));
}
__device__ __forceinline__ void cp_async16(uint32_t smem, const void* gptr) {
    asm volatile("cp.async.cg.shared.global [%0], [%1], 16;" :: "r"(smem), "l"(gptr) : "memory");
}
__device__ __forceinline__ void cp_commit_wait() {
    asm volatile("cp.async.commit_group;\ncp.async.wait_group 0;" ::: "memory");
}

// ============ gi GEMM role: 2-buffer smem pipeline, reg prefetch ============
// Identical arithmetic to the verified R13 gi (same tiling, same MMA order);
// only the staging is pipelined: LDG c+1 overlaps MMA c, one sync per chunk.
__device__ void gi_role(unsigned char* smraw, int g,
                        const float* __restrict__ X,
                        const float* __restrict__ W,
                        const float* __restrict__ bih) {
    unsigned* gsm = (unsigned*)smraw;     // 2 stages x [Ahi|Alo|Bhi|Blo] x 4608

    const int bx = g & 7;                 // n-tile
    const int by = g >> 3;                // m-tile = time pair
    const int tid  = threadIdx.x;
    const int lane = tid & 31;
    const int wid  = tid >> 5;
    const int warpM = (wid & 3) * 32;
    const int warpN = (wid >> 2) * 32;
    const int Mb = by * 128;
    const int Nb = bx * 128;

    const int aRow = warpM + (lane & 15);
    const int aColOff = (lane >> 4) << 2;
    const int bRow = warpN + ((lane >> 4) << 3) + (lane & 7);
    const int bColOff = ((lane >> 3) & 1) << 2;

    float acc[2][4][4];
    #pragma unroll
    for (int mt = 0; mt < 2; mt++)
        #pragma unroll
        for (int nt = 0; nt < 4; nt++)
            #pragma unroll
            for (int i = 0; i < 4; i++) acc[mt][nt][i] = 0.f;

    const int srow = tid >> 3;            // 0..63
    const int sc4  = (tid & 7) * 4;       // 0..28

    float4 ar[2], br[2];                  // register prefetch (2 rows each)

    auto load_chunk = [&](int c) {
        const int k0 = c * GI_KC;
        #pragma unroll
        for (int i = 0; i < 2; i++) {
            const int row = srow + 64 * i;
            ar[i] = *(const float4*)&X[(size_t)(Mb + row) * IN_F + k0 + sc4];
            br[i] = *(const float4*)&W[(size_t)(Nb + row) * IN_F + k0 + sc4];
        }
    };
    auto store_chunk = [&](int st) {
        unsigned* Ahi = gsm + st * (4 * PLANE_U);
        unsigned* Alo = Ahi + PLANE_U;
        unsigned* Bhi = Ahi + 2 * PLANE_U;
        unsigned* Blo = Ahi + 3 * PLANE_U;
        #pragma unroll
        for (int i = 0; i < 2; i++) {
            const int row = srow + 64 * i;
            uint4 ah, al, bh, bl;
            cvt_split(ar[i].x, ah.x, al.x); cvt_split(ar[i].y, ah.y, al.y);
            cvt_split(ar[i].z, ah.z, al.z); cvt_split(ar[i].w, ah.w, al.w);
            cvt_split(br[i].x, bh.x, bl.x); cvt_split(br[i].y, bh.y, bl.y);
            cvt_split(br[i].z, bh.z, bl.z); cvt_split(br[i].w, bh.w, bl.w);
            const int off = row * GSTRIDE + sc4;
            *(uint4*)&Ahi[off] = ah;
            *(uint4*)&Alo[off] = al;
            *(uint4*)&Bhi[off] = bh;
            *(uint4*)&Blo[off] = bl;
        }
    };

    load_chunk(0);
    store_chunk(0);
    __syncthreads();

    for (int c = 0; c < N_CHUNKS; c++) {
        if (c + 1 < N_CHUNKS) load_chunk(c + 1);   // LDG in flight over MMA

        unsigned* Ahi = gsm + (c & 1) * (4 * PLANE_U);
        unsigned* Alo = Ahi + PLANE_U;
        unsigned* Bhi = Ahi + 2 * PLANE_U;
        unsigned* Blo = Ahi + 3 * PLANE_U;

        #pragma unroll
        for (int k8 = 0; k8 < GI_KC / 8; k8++) {
            const int kb = k8 * 8;
            unsigned ah[2][4], al[2][4], bh[4][2], bl[4][2];
            #pragma unroll
            for (int mt = 0; mt < 2; mt++) {
                const int off = (aRow + mt * 16) * GSTRIDE + kb + aColOff;
                ldsm4(ah[mt], smem_u32(&Ahi[off]));
                ldsm4(al[mt], smem_u32(&Alo[off]));
            }
            #pragma unroll
            for (int np = 0; np < 2; np++) {
                const int off = (bRow + np * 16) * GSTRIDE + kb + bColOff;
                unsigned r[4];
                ldsm4(r, smem_u32(&Bhi[off]));
                bh[2 * np][0] = r[0]; bh[2 * np][1] = r[1];
                bh[2 * np + 1][0] = r[2]; bh[2 * np + 1][1] = r[3];
                ldsm4(r, smem_u32(&Blo[off]));
                bl[2 * np][0] = r[0]; bl[2 * np][1] = r[1];
                bl[2 * np + 1][0] = r[2]; bl[2 * np + 1][1] = r[3];
            }
            #pragma unroll
            for (int mt = 0; mt < 2; mt++)
                #pragma unroll
                for (int nt = 0; nt < 4; nt++) {
                    mma_tf32(acc[mt][nt], ah[mt], bh[nt]);
                    mma_tf32(acc[mt][nt], ah[mt], bl[nt]);
                    mma_tf32(acc[mt][nt], al[mt], bh[nt]);
                }
        }

        if (c + 1 < N_CHUNKS) {
            store_chunk((c + 1) & 1);   // other buffer; last read at MMA c-1
            __syncthreads();
        }
    }

    #pragma unroll
    for (int mt = 0; mt < 2; mt++)
        #pragma unroll
        for (int nt = 0; nt < 4; nt++) {
            const int gr = Mb + warpM + mt * 16 + (lane >> 2);
            const int gc = Nb + warpN + nt * 8 + 2 * (lane & 3);
            const float2 bv = *(const float2*)&bih[gc];
            float2 v0, v1;
            v0.x = acc[mt][nt][0] + bv.x; v0.y = acc[mt][nt][1] + bv.y;
            v1.x = acc[mt][nt][2] + bv.x; v1.y = acc[mt][nt][3] + bv.y;
            *(float2*)&g_gi[(size_t)gr * GATES + gc] = v0;
            *(float2*)&g_gi[(size_t)(gr + 8) * GATES + gc] = v1;
        }

    __threadfence();
    __syncthreads();
    if (tid == 0) red_release_gpu_add1(&g_gi_cnt[by * 8]);
}

// ===================== scan role (byte-identical to R13, 1702us) ==========
__device__ void scan_role(unsigned char* smraw,
                          const float* __restrict__ Whh,
                          const float* __restrict__ bhh,
                          float* __restrict__ out) {
    unsigned short* hhi = (unsigned short*)smraw;
    unsigned short* hlo = hhi + PLANE_USH;
    float* red = (float*)(smraw + RED_OFF_B);

    const int tid  = threadIdx.x;
    const int lane = tid & 31;
    const int wid  = tid >> 5;
    const int ksl  = wid >> 2;
    const int ng   = wid & 3;
    const int grp  = blockIdx.x >> 4;
    const int cg   = blockIdx.x & 15;
    const int bg0  = grp * GB;
    const int j0   = cg * CTA_COLS;
    unsigned* bar  = &g_bars[grp * 32];

    unsigned short* Whi_s = hhi;
    unsigned short* Wlo_s = hhi + 64 * HROW;
    for (int i = tid; i < 64 * 512; i += 512) {
        const int n = i >> 9, c = i & 511;
        const int gr = (n < CTA_COLS) ? (j0 + n) : (HID + j0 + (n - CTA_COLS));
        const float w = Whh[(size_t)gr * HID + c];
        const __nv_bfloat16 h16 = __float2bfloat16(w);
        const __nv_bfloat16 l16 = __float2bfloat16(w - __bfloat162float(h16));
        Whi_s[n * HROW + c] = __bfloat16_as_ushort(h16);
        Wlo_s[n * HROW + c] = __bfloat16_as_ushort(l16);
    }
    __syncthreads();
    unsigned wbh[8][4], wbl[8][4];
    {
        const int brow = ng * 16 + (lane & 7) + ((lane >> 4) << 3);
        const int bcol = ((lane >> 3) & 1) * 8;
        #pragma unroll
        for (int s = 0; s < 8; s++) {
            const int k0 = ksl * 128 + s * 16;
            ldsm4(wbh[s], smem_u32(&Whi_s[brow * HROW + k0 + bcol]));
            ldsm4(wbl[s], smem_u32(&Wlo_s[brow * HROW + k0 + bcol]));
        }
    }
    __syncthreads();

    const int arow  = (lane & 7) + 8 * ((lane >> 3) & 1);
    const int acol8 = (lane >> 4) * 8;
    const uint32_t ahi_base = smem_u32(&hhi[arow * HROW]);
    const uint32_t alo_base = smem_u32(&hlo[arow * HROW]);

    const int jl = tid & 31;
    const int bl = tid >> 5;
    const int b  = bg0 + bl;
    const int jg = j0 + jl;
    const float bhf = bhh[jg];
    const float bhn = bhh[HID + jg];

    if (tid == 0) {
        while (ld_acquire_gpu(&g_gi_cnt[0]) < 8) __nanosleep(64);
    }
    __syncthreads();
    int last_ready = 0;

    float gif = g_gi[((size_t)b << 10) + jg];
    float gin = g_gi[((size_t)b << 10) + HID + jg];

    for (int t = 0; t < T_STEPS; t++) {
        if (t > 0) {
            __syncthreads();
            if (tid == 0) {
                red_release_gpu_add1(bar);
                const unsigned target = (unsigned)GROUP_CTAS * (unsigned)t;
                while (ld_acquire_gpu(bar) < target) __nanosleep(32);
                const int qn = ((t + 1 < T_STEPS) ? (t + 1) : t) >> 1;
                if (qn > last_ready) {
                    while (ld_acquire_gpu(&g_gi_cnt[qn * 8]) < 8) __nanosleep(32);
                    last_ready = qn;
                }
            }
            __syncthreads();
        }

        const int tn = (t + 1 < T_STEPS) ? (t + 1) : t;
        const float gif_n = g_gi[((size_t)tn << 16) + ((size_t)b << 10) + jg];
        const float gin_n = g_gi[((size_t)tn << 16) + ((size_t)b << 10) + HID + jg];

        float accf = 0.f, accn = 0.f;
        if (t > 0) {
            const unsigned short* ph = g_hhi + ((size_t)(t - 1) * BATCH + bg0) * HID;
            const unsigned short* pl = g_hlo + ((size_t)(t - 1) * BATCH + bg0) * HID;
            #pragma unroll
            for (int i = 0; i < 2; i++) {
                const int idx = tid + 512 * i;
                const int br = idx >> 6, c = idx & 63;
                cp_async16(smem_u32(&hhi[br * HROW + c * 8]), ph + idx * 8);
                cp_async16(smem_u32(&hlo[br * HROW + c * 8]), pl + idx * 8);
            }
            cp_commit_wait();
            __syncthreads();

            float c4[2][4] = {{0.f, 0.f, 0.f, 0.f}, {0.f, 0.f, 0.f, 0.f}};
            #pragma unroll
            for (int s = 0; s < 8; s++) {
                const int k0 = ksl * 128 + s * 16;
                unsigned ah[4], al[4];
                ldsm4(ah, ahi_base + (k0 + acol8) * 2);
                ldsm4(al, alo_base + (k0 + acol8) * 2);
                #pragma unroll
                for (int nt = 0; nt < 2; nt++) {
                    mma_bf16(c4[nt], ah, &wbh[s][2 * nt]);
                    mma_bf16(c4[nt], ah, &wbl[s][2 * nt]);
                    mma_bf16(c4[nt], al, &wbh[s][2 * nt]);
                }
            }
            const int rm = lane >> 2;
            const int rn = ng * 16 + 2 * (lane & 3);
            #pragma unroll
            for (int nt = 0; nt < 2; nt++) {
                *(float2*)&red[ksl * (GB * 64) + rm * 64 + rn + nt * 8] =
                    make_float2(c4[nt][0], c4[nt][1]);
                *(float2*)&red[ksl * (GB * 64) + (rm + 8) * 64 + rn + nt * 8] =
                    make_float2(c4[nt][2], c4[nt][3]);
            }
            __syncthreads();

            #pragma unroll
            for (int k = 0; k < 4; k++) {
                accf += red[k * (GB * 64) + bl * 64 + jl];
                accn += red[k * (GB * 64) + bl * 64 + CTA_COLS + jl];
            }
        }

        {
            const float f  = 1.f / (1.f + expf(-(gif + accf + bhf)));
            const float hv = tanhf(gin + f * (accn + bhn));
            out[((size_t)t * BATCH + b) * HID + jg] = hv;
            const __nv_bfloat16 h16 = __float2bfloat16(hv);
            const __nv_bfloat16 l16 = __float2bfloat16(hv - __bfloat162float(h16));
            g_hhi[(size_t)t * BATCH * HID + b * HID + jg] = __bfloat16_as_ushort(h16);
            g_hlo[(size_t)t * BATCH * HID + b * HID + jg] = __bfloat16_as_ushort(l16);
        }
        gif = gif_n;
        gin = gin_n;
    }

    __syncthreads();
    if (tid == 0) {
        const unsigned r = atomicAdd(bar, 1u);
        if (r == (unsigned)GROUP_CTAS * (unsigned)T_STEPS - 1u)
            *((volatile unsigned*)bar) = 0u;
        red_release_gpu_add1(&g_scan_done);
        if (blockIdx.x == 0) {
            while (ld_acquire_gpu(&g_scan_done) < (unsigned)SCAN_BLOCKS) __nanosleep(64);
            for (int q = 0; q < 256; q++)
                *((volatile unsigned*)&g_gi_cnt[q * 8]) = 0u;
            *((volatile unsigned*)&g_scan_done) = 0u;
        }
    }
}

// ===================== fused kernel =====================
__global__ __launch_bounds__(512) void fused_mgu(const float* __restrict__ X,
                                                 const float* __restrict__ Wih,
                                                 const float* __restrict__ bih,
                                                 const float* __restrict__ Whh,
                                                 const float* __restrict__ bhh,
                                                 float* __restrict__ out) {
    extern __shared__ unsigned char smraw[];
    if (blockIdx.x < SCAN_BLOCKS) {
        scan_role(smraw, Whh, bhh, out);
    } else {
        gi_role(smraw, (int)blockIdx.x - SCAN_BLOCKS, X, Wih, bih);
    }
}

extern "C" void kernel_launch(void* const* d_in, const int* in_sizes, int n_in,
                              void* d_out, int out_size) {
    const float* X   = (const float*)d_in[0];  // (512, 64, 512)
    const float* Wih = (const float*)d_in[1];  // (1024, 512)
    const float* Whh = (const float*)d_in[2];  // (1024, 512)
    const float* bih = (const float*)d_in[3];  // (1024,)
    const float* bhh = (const float*)d_in[4];  // (1024,)
    float* out = (float*)d_out;                // (512, 64, 512)

    cudaFuncSetAttribute(fused_mgu,
                         cudaFuncAttributeMaxDynamicSharedMemorySize, FUSED_SMEM_BYTES);

    fused_mgu<<<SCAN_BLOCKS + GI_BLOCKS, 512, FUSED_SMEM_BYTES>>>(
        X, Wih, bih, Whh, bhh, out);
}